// round 14
// baseline (speedup 1.0000x reference)
#include <cuda_runtime.h>

// Output is identically zero: g = -sum((x - x)^2) == 0 elementwise, so
// w = C*g == 0 and lambda_tri = mask @ w == 0. Kernel = 64 KB zero-fill.
//
// CONVERGED — holding. Evidence across 13 rounds:
//  - Node type: kernel node == native memset node (R1/R2).
//  - Per-thread work: 1 STG.128/thread optimal (R3 single-SM regression).
//  - Grid shape: 1-blk and 128-blk are real regressions; 16/32/64-block
//    shapes indistinguishable. 32x128 locked in.
//  - Identical binary, 8 samples: wall {4.608, 5.440, 4.864, 4.576, 5.888,
//    4.608, 4.832, 4.832}us (mean ~4.96, sigma ~0.42); device {3.33, 3.62,
//    3.62, 3.36, 3.58, 3.04, 3.55, 3.36}us. Stationary jitter, identical SASS.
// Remaining time = launch ramp (~3.3us) + graph replay (~1.5us); 8ns of store
// traffic cannot be made cheaper than the launch that carries it.

__global__ __launch_bounds__(128, 1)
void zero_fill(float4* __restrict__ out) {
    // 32 blocks x 128 threads = 4096 float4 = 16384 floats = 64 KB.
    out[(blockIdx.x << 7) | threadIdx.x] = make_float4(0.f, 0.f, 0.f, 0.f);
}

__global__ void zero_generic(float* __restrict__ out, int n) {
    int i = blockIdx.x * blockDim.x + threadIdx.x;
    if (i < n) out[i] = 0.f;
}

extern "C" void kernel_launch(void* const* d_in, const int* in_sizes, int n_in,
                              void* d_out, int out_size) {
    (void)d_in; (void)in_sizes; (void)n_in;
    if (out_size == 16384) {
        zero_fill<<<32, 128>>>((float4*)d_out);
    } else {
        int threads = 256;
        int blocks = (out_size + threads - 1) / threads;
        zero_generic<<<blocks, threads>>>((float*)d_out, out_size);
    }
}

// round 15
// speedup vs baseline: 1.0629x; 1.0629x over previous
#include <cuda_runtime.h>

// Output is identically zero: g = -sum((x - x)^2) == 0 elementwise, so
// w = C*g == 0 and lambda_tri = mask @ w == 0. Kernel = 64 KB zero-fill.
//
// CONVERGED — holding. Evidence across 14 rounds:
//  - Node type: kernel node == native memset node (R1/R2).
//  - Per-thread work: 1 STG.128/thread optimal (R3 single-SM regression).
//  - Grid shape: 1-blk and 128-blk are real regressions; 16/32/64-block
//    shapes indistinguishable. 32x128 locked in.
//  - Identical binary, 9 samples: wall {4.608, 5.440, 4.864, 4.576, 5.888,
//    4.608, 4.832, 4.832, 4.864}us (mean ~4.95, sigma ~0.40); device
//    3.04-3.62us. Stationary jitter, byte-identical SASS every round.
// Remaining time = launch ramp (~3.3us) + graph replay (~1.5us); 8ns of store
// traffic cannot be made cheaper than the launch that carries it.

__global__ __launch_bounds__(128, 1)
void zero_fill(float4* __restrict__ out) {
    // 32 blocks x 128 threads = 4096 float4 = 16384 floats = 64 KB.
    out[(blockIdx.x << 7) | threadIdx.x] = make_float4(0.f, 0.f, 0.f, 0.f);
}

__global__ void zero_generic(float* __restrict__ out, int n) {
    int i = blockIdx.x * blockDim.x + threadIdx.x;
    if (i < n) out[i] = 0.f;
}

extern "C" void kernel_launch(void* const* d_in, const int* in_sizes, int n_in,
                              void* d_out, int out_size) {
    (void)d_in; (void)in_sizes; (void)n_in;
    if (out_size == 16384) {
        zero_fill<<<32, 128>>>((float4*)d_out);
    } else {
        int threads = 256;
        int blocks = (out_size + threads - 1) / threads;
        zero_generic<<<blocks, threads>>>((float*)d_out, out_size);
    }
}